// round 5
// baseline (speedup 1.0000x reference)
#include <cuda_runtime.h>
#include <math.h>

#define N_MAX (128 * 128 * 128)
#define TPB 256
#define NB_MAX 32768
#define BSHIFT 7     // bucket = idx >> 7  (128 entries per bucket)

// Static scratch (no allocations).
__device__ unsigned g_hist[NB_MAX];            // bucket histogram
__device__ unsigned g_off[NB_MAX];             // bucket offsets (scan, then bumped)
__device__ unsigned g_idxarr[N_MAX];           // hash index per point
__device__ unsigned g_sidx[N_MAX];             // hash indices in sorted order
__device__ unsigned g_rank[N_MAX];             // point i -> sorted position j
__device__ float4   g_rec[(size_t)N_MAX * 4];  // 64B record per point (sorted order)
__device__ double   g_sum, g_sumsq;
__device__ float2   g_stats;                   // x = mean, y = (2*far/vs/6)/std

__device__ __forceinline__ unsigned hash_idx(unsigned c0, unsigned c1, unsigned c2,
                                             unsigned tsize) {
    unsigned h = (c0 * 1u) ^ (c1 * 2654435761u) ^ (c2 * 805459861u);
    return h % tsize;
}

__device__ __forceinline__ float sigmoidf_(float x) {
    return 1.0f / (1.0f + expf(-x));
}

__global__ void k_zero() {
    int i = blockIdx.x * blockDim.x + threadIdx.x;
    if (i < NB_MAX) g_hist[i] = 0u;
    if (i == 0) { g_sum = 0.0; g_sumsq = 0.0; }
}

// Hash every point, build bucket histogram.
__global__ void __launch_bounds__(TPB) k_hash_hist(const int* __restrict__ coords,
                                                   int n, unsigned tsize) {
    int i = blockIdx.x * TPB + threadIdx.x;
    if (i >= n) return;
    unsigned c0 = (unsigned)coords[3 * i + 0];
    unsigned c1 = (unsigned)coords[3 * i + 1];
    unsigned c2 = (unsigned)coords[3 * i + 2];
    unsigned idx = hash_idx(c0, c1, c2, tsize);
    g_idxarr[i] = idx;
    atomicAdd(&g_hist[idx >> BSHIFT], 1u);
}

// Exclusive scan of g_hist -> g_off. One block, 1024 threads, 32 items each.
// Two-pass over items (no per-thread local array -> tiny register use).
__global__ void __launch_bounds__(1024) k_scan(int nb) {
    __shared__ unsigned sh[1024];
    int t = threadIdx.x;
    int base = t * 32;

    unsigned s = 0;
    #pragma unroll
    for (int k = 0; k < 32; k++)
        if (base + k < nb) s += g_hist[base + k];
    sh[t] = s;
    __syncthreads();
    for (int o = 1; o < 1024; o <<= 1) {
        unsigned v = (t >= o) ? sh[t - o] : 0u;
        __syncthreads();
        sh[t] += v;
        __syncthreads();
    }
    unsigned run = (t == 0) ? 0u : sh[t - 1];
    #pragma unroll
    for (int k = 0; k < 32; k++) {
        if (base + k < nb) {
            g_off[base + k] = run;
            run += g_hist[base + k];
        }
    }
}

// Scatter: place each point's idx at its sorted slot; record inverse perm.
__global__ void __launch_bounds__(TPB) k_scatter(int n) {
    int i = blockIdx.x * TPB + threadIdx.x;
    if (i >= n) return;
    unsigned idx = g_idxarr[i];
    unsigned pos = atomicAdd(&g_off[idx >> BSHIFT], 1u);
    g_sidx[pos] = idx;      // scattered 4B (within-bucket range)
    g_rank[i]   = pos;      // coalesced
}

// Main gather, in sorted-index order: warp-local table locality.
// Computes everything except the stats-dependent mean shift. Writes a 64B
// record per point (coalesced at sorted position j) + reduces stats.
__global__ void __launch_bounds__(TPB) k_gather(const float* __restrict__ table,
                                                const float* __restrict__ far_p,
                                                const int* __restrict__ vs_p,
                                                int n, unsigned tsize) {
    __shared__ __align__(16) float4 st[TPB * 4];
    int t = threadIdx.x;
    int j = blockIdx.x * TPB + t;

    float f  = __ldg(far_p);
    float vs = (float)__ldg(vs_p);
    float a  = 2.0f * f / vs;

    float s = 0.0f, ss = 0.0f;
    if (j < n) {
        unsigned idx = g_sidx[j];
        const float* tb = table;
        float g0 = __ldg(tb + idx);
        float g1 = __ldg(tb + (size_t)tsize + idx);
        float g2 = __ldg(tb + 2 * (size_t)tsize + idx);
        float q0 = __ldg(tb + 3 * (size_t)tsize + idx);
        float q1 = __ldg(tb + 4 * (size_t)tsize + idx);
        float q2 = __ldg(tb + 5 * (size_t)tsize + idx);
        float q3 = __ldg(tb + 6 * (size_t)tsize + idx);
        float s0 = __ldg(tb + 7 * (size_t)tsize + idx);
        float s1 = __ldg(tb + 8 * (size_t)tsize + idx);
        float s2 = __ldg(tb + 9 * (size_t)tsize + idx);
        float h0 = __ldg(tb + 10 * (size_t)tsize + idx);
        float h1 = __ldg(tb + 11 * (size_t)tsize + idx);
        float h2 = __ldg(tb + 12 * (size_t)tsize + idx);
        float od = __ldg(tb + 13 * (size_t)tsize + idx);

        s  = g0 + g1 + g2;
        ss = g0 * g0 + g1 * g1 + g2 * g2;

        float rn = rsqrtf(q0 * q0 + q1 * q1 + q2 * q2 + q3 * q3);
        float r = q0 * rn, x = q1 * rn, y = q2 * rn, z = q3 * rn;
        float R00 = 1.0f - 2.0f * (y * y + z * z);
        float R01 = 2.0f * (x * y - r * z);
        float R02 = 2.0f * (x * z + r * y);
        float R10 = 2.0f * (x * y + r * z);
        float R11 = 1.0f - 2.0f * (x * x + z * z);
        float R12 = 2.0f * (y * z - r * x);
        float R20 = 2.0f * (x * z - r * y);
        float R21 = 2.0f * (y * z + r * x);
        float R22 = 1.0f - 2.0f * (x * x + y * y);

        float sc0 = sigmoidf_(s0) * a;
        float sc1 = sigmoidf_(s1) * a;
        float sc2 = sigmoidf_(s2) * a;
        float v0 = sc0 * sc0, v1 = sc1 * sc1, v2 = sc2 * sc2;

        float c00 = R00 * R00 * v0 + R01 * R01 * v1 + R02 * R02 * v2;
        float c01 = R00 * R10 * v0 + R01 * R11 * v1 + R02 * R12 * v2;
        float c02 = R00 * R20 * v0 + R01 * R21 * v1 + R02 * R22 * v2;
        float c11 = R10 * R10 * v0 + R11 * R11 * v1 + R12 * R12 * v2;
        float c12 = R10 * R20 * v0 + R11 * R21 * v1 + R12 * R22 * v2;
        float c22 = R20 * R20 * v0 + R21 * R21 * v1 + R22 * R22 * v2;

        float op = 1.0f / (1.0f + expf(4.0f - od));

        st[t * 4 + 0] = make_float4(g0, g1, g2, h0);
        st[t * 4 + 1] = make_float4(h1, h2, op, c00);
        st[t * 4 + 2] = make_float4(c01, c02, c11, c12);
        st[t * 4 + 3] = make_float4(c22, 0.0f, 0.0f, 0.0f);
    }

    // stats reduction
    #pragma unroll
    for (int o = 16; o > 0; o >>= 1) {
        s  += __shfl_down_sync(0xFFFFFFFFu, s,  o);
        ss += __shfl_down_sync(0xFFFFFFFFu, ss, o);
    }
    __shared__ double sh_s[8], sh_ss[8];
    int lane = t & 31, w = t >> 5;
    if (lane == 0) { sh_s[w] = (double)s; sh_ss[w] = (double)ss; }
    __syncthreads();
    if (t == 0) {
        double ts = 0.0, tss = 0.0;
        for (int k = 0; k < TPB / 32; k++) { ts += sh_s[k]; tss += sh_ss[k]; }
        atomicAdd(&g_sum, ts);
        atomicAdd(&g_sumsq, tss);
    }

    // coalesced streaming write of this block's record slab
    int blk = min(TPB, n - blockIdx.x * TPB);
    size_t base = (size_t)blockIdx.x * TPB * 4;
    int cnt = blk * 4;
    for (int k = t; k < cnt; k += TPB)
        __stcs(&g_rec[base + k], st[k]);
}

__global__ void k_stats(const float* __restrict__ far_p,
                        const int* __restrict__ vs_p, int n) {
    double M    = 3.0 * (double)n;
    double mean = g_sum / M;
    double var  = (g_sumsq - g_sum * g_sum / M) / (M - 1.0);   // ddof = 1
    float stdv  = (float)sqrt(var);
    float f     = far_p[0];
    float vs    = (float)vs_p[0];
    float a     = 2.0f * f / vs;
    g_stats = make_float2((float)mean, a / (6.0f * stdv));
}

// Unpermute + finalize: 4 lanes cooperatively fetch each point's 64B record
// (1 wavefront/point), then finish means and write all outputs coalesced.
__global__ void __launch_bounds__(TPB) k_layout(const int* __restrict__ coords,
                                                const float* __restrict__ cam,
                                                const float* __restrict__ far_p,
                                                const int* __restrict__ vs_p,
                                                float* __restrict__ out,
                                                int n) {
    __shared__ __align__(16) float4 shr[TPB * 4];   // 16 KB records
    __shared__ __align__(16) float  sh_c[TPB * 9];  // cov staging
    __shared__ __align__(16) float  sh_m[TPB * 3];
    __shared__ __align__(16) float  sh_h[TPB * 3];

    int t  = threadIdx.x;
    int p0 = blockIdx.x * TPB;

    // Phase A: cooperative record fetch (quad of lanes per point)
    int gid = t >> 2, q = t & 3;
    #pragma unroll
    for (int it = 0; it < 4; it++) {
        int pl = it * 64 + gid;
        int p  = p0 + pl;
        if (p < n) {
            unsigned r = g_rank[p];
            shr[pl * 4 + q] = g_rec[(size_t)r * 4 + q];
        }
    }
    __syncthreads();

    int i = p0 + t;
    float op = 0.0f;
    if (i < n) {
        float f  = __ldg(far_p);
        float vs = (float)__ldg(vs_p);
        float aa = 2.0f * f / vs;
        float off = -f + f / vs;
        float2 st = g_stats;
        float cm0 = __ldg(cam + 0), cm1 = __ldg(cam + 1), cm2 = __ldg(cam + 2);

        float4 ra = shr[t * 4 + 0];   // dm0 dm1 dm2 h0
        float4 rb = shr[t * 4 + 1];   // h1 h2 op c00
        float4 rc = shr[t * 4 + 2];   // c01 c02 c11 c12
        float4 rd = shr[t * 4 + 3];   // c22 - - -

        int c0 = coords[3 * i + 0];
        int c1 = coords[3 * i + 1];
        int c2 = coords[3 * i + 2];

        sh_m[t * 3 + 0] = (ra.x - st.x) * st.y + (float)c0 * aa + cm0 + off;
        sh_m[t * 3 + 1] = (ra.y - st.x) * st.y + (float)c1 * aa + cm1 + off;
        sh_m[t * 3 + 2] = (ra.z - st.x) * st.y + (float)c2 * aa + cm2 + off;

        sh_h[t * 3 + 0] = ra.w;
        sh_h[t * 3 + 1] = rb.x;
        sh_h[t * 3 + 2] = rb.y;

        float* pc = sh_c + t * 9;
        pc[0] = rb.w; pc[1] = rc.x; pc[2] = rc.y;
        pc[3] = rc.x; pc[4] = rc.z; pc[5] = rc.w;
        pc[6] = rc.y; pc[7] = rc.w; pc[8] = rd.x;

        op = rb.z;
    }
    __syncthreads();

    float* means = out;
    float* cov   = out + 3  * (size_t)n;
    float* harm  = out + 12 * (size_t)n;
    float* opac  = out + 15 * (size_t)n;

    int blk = min(TPB, n - p0);
    if (blk == TPB) {
        const float4* sm4 = (const float4*)sh_m;
        const float4* sh4 = (const float4*)sh_h;
        const float4* sc4 = (const float4*)sh_c;
        float4* dm4 = (float4*)(means + (size_t)p0 * 3);
        float4* dh4 = (float4*)(harm  + (size_t)p0 * 3);
        float4* dc4 = (float4*)(cov   + (size_t)p0 * 9);
        for (int k = t; k < TPB * 3 / 4; k += TPB) {
            __stcs(dm4 + k, sm4[k]);
            __stcs(dh4 + k, sh4[k]);
        }
        for (int k = t; k < TPB * 9 / 4; k += TPB)
            __stcs(dc4 + k, sc4[k]);
    } else {
        for (int k = t; k < blk * 3; k += TPB) {
            __stcs(means + (size_t)p0 * 3 + k, sh_m[k]);
            __stcs(harm  + (size_t)p0 * 3 + k, sh_h[k]);
        }
        for (int k = t; k < blk * 9; k += TPB)
            __stcs(cov + (size_t)p0 * 9 + k, sh_c[k]);
    }
    if (i < n) __stcs(opac + i, op);
}

extern "C" void kernel_launch(void* const* d_in, const int* in_sizes, int n_in,
                              void* d_out, int out_size) {
    const int*   coords = (const int*)d_in[0];
    const float* table  = (const float*)d_in[1];
    const float* cam    = (const float*)d_in[2];
    const float* far_p  = (const float*)d_in[3];
    const int*   vs_p   = (const int*)d_in[4];
    float*       out    = (float*)d_out;

    int n = in_sizes[0] / 3;
    unsigned tsize = (unsigned)(in_sizes[1] / 14);
    int nb = (int)((tsize + ((1u << BSHIFT) - 1)) >> BSHIFT);
    if (nb > NB_MAX) nb = NB_MAX;   // fixed shape: 4194304 >> 7 = 32768

    int blocks = (n + TPB - 1) / TPB;

    k_zero     <<<(NB_MAX + TPB - 1) / TPB, TPB>>>();
    k_hash_hist<<<blocks, TPB>>>(coords, n, tsize);
    k_scan     <<<1, 1024>>>(nb);
    k_scatter  <<<blocks, TPB>>>(n);
    k_gather   <<<blocks, TPB>>>(table, far_p, vs_p, n, tsize);
    k_stats    <<<1, 1>>>(far_p, vs_p, n);
    k_layout   <<<blocks, TPB>>>(coords, cam, far_p, vs_p, out, n);
}

// round 6
// speedup vs baseline: 1.4885x; 1.4885x over previous
#include <cuda_runtime.h>
#include <math.h>

#define N_MAX  (128 * 128 * 128)
#define T_MAX  4194304u
#define TPB    256

// Static scratch (no allocations).
__device__ unsigned g_idx[N_MAX];                  // 8 MB  hash index per point
__device__ unsigned g_cnt[T_MAX];                  // 16 MB per-entry reference count
__device__ float4   g_aos[(size_t)T_MAX * 4];      // 268 MB AoS records (64B/entry)
__device__ double   g_sum, g_sumsq;
__device__ float2   g_stats;                       // x = mean, y = (2*far/vs/6)/std

__device__ __forceinline__ unsigned hash_idx(unsigned c0, unsigned c1, unsigned c2,
                                             unsigned tsize) {
    unsigned h = (c0 * 1u) ^ (c1 * 2654435761u) ^ (c2 * 805459861u);
    return h % tsize;
}

__device__ __forceinline__ float sigmoidf_(float x) {
    return 1.0f / (1.0f + expf(-x));
}

// Zero the count array (16 MB) + stat accumulators.
__global__ void __launch_bounds__(TPB) k_zero(unsigned tsize) {
    unsigned i = blockIdx.x * TPB + threadIdx.x;
    uint4* c4 = (uint4*)g_cnt;
    if (i < tsize / 4) c4[i] = make_uint4(0u, 0u, 0u, 0u);
    if (i == 0) { g_sum = 0.0; g_sumsq = 0.0; }
}

// Hash every point; build per-entry reference counts (no-return atomics).
__global__ void __launch_bounds__(TPB) k_hash_count(const int* __restrict__ coords,
                                                    int n, unsigned tsize) {
    int i = blockIdx.x * TPB + threadIdx.x;
    if (i >= n) return;
    unsigned c0 = (unsigned)coords[3 * i + 0];
    unsigned c1 = (unsigned)coords[3 * i + 1];
    unsigned c2 = (unsigned)coords[3 * i + 2];
    unsigned idx = hash_idx(c0, c1, c2, tsize);
    g_idx[i] = idx;
    atomicAdd(&g_cnt[idx], 1u);
}

// Streaming SoA->AoS transpose of the table, fused with the global stats
// reduction (rows 0-2 weighted by reference count). Each thread handles 4
// consecutive entries (float4 per row). Skips stores for never-referenced
// entries (~61%), cutting write traffic 268 MB -> ~105 MB.
__global__ void __launch_bounds__(TPB) k_transpose(const float* __restrict__ table,
                                                   unsigned tsize) {
    unsigned t  = threadIdx.x;
    unsigned e4 = (blockIdx.x * TPB + t);        // group of 4 entries
    unsigned e  = e4 * 4;

    float4 v[14];
    #pragma unroll
    for (int r = 0; r < 14; r++)
        v[r] = __ldg((const float4*)(table + (size_t)r * tsize) + e4);

    uint4 c = *((const uint4*)g_cnt + e4);

    // stats: sum/sumsq of rows 0-2, weighted by count
    float s = 0.0f, ss = 0.0f;
    {
        float c0 = (float)c.x, c1 = (float)c.y, c2 = (float)c.z, c3 = (float)c.w;
        s  += c0 * (v[0].x + v[1].x + v[2].x);
        s  += c1 * (v[0].y + v[1].y + v[2].y);
        s  += c2 * (v[0].z + v[1].z + v[2].z);
        s  += c3 * (v[0].w + v[1].w + v[2].w);
        ss += c0 * (v[0].x * v[0].x + v[1].x * v[1].x + v[2].x * v[2].x);
        ss += c1 * (v[0].y * v[0].y + v[1].y * v[1].y + v[2].y * v[2].y);
        ss += c2 * (v[0].z * v[0].z + v[1].z * v[1].z + v[2].z * v[2].z);
        ss += c3 * (v[0].w * v[0].w + v[1].w * v[1].w + v[2].w * v[2].w);
    }

    // AoS records (only for referenced entries)
    float4* rec = g_aos + (size_t)e * 4;
    if (c.x) {
        __stcs(rec + 0,  make_float4(v[0].x, v[1].x, v[2].x,  v[3].x));
        __stcs(rec + 1,  make_float4(v[4].x, v[5].x, v[6].x,  v[7].x));
        __stcs(rec + 2,  make_float4(v[8].x, v[9].x, v[10].x, v[11].x));
        __stcs(rec + 3,  make_float4(v[12].x, v[13].x, 0.0f, 0.0f));
    }
    if (c.y) {
        __stcs(rec + 4,  make_float4(v[0].y, v[1].y, v[2].y,  v[3].y));
        __stcs(rec + 5,  make_float4(v[4].y, v[5].y, v[6].y,  v[7].y));
        __stcs(rec + 6,  make_float4(v[8].y, v[9].y, v[10].y, v[11].y));
        __stcs(rec + 7,  make_float4(v[12].y, v[13].y, 0.0f, 0.0f));
    }
    if (c.z) {
        __stcs(rec + 8,  make_float4(v[0].z, v[1].z, v[2].z,  v[3].z));
        __stcs(rec + 9,  make_float4(v[4].z, v[5].z, v[6].z,  v[7].z));
        __stcs(rec + 10, make_float4(v[8].z, v[9].z, v[10].z, v[11].z));
        __stcs(rec + 11, make_float4(v[12].z, v[13].z, 0.0f, 0.0f));
    }
    if (c.w) {
        __stcs(rec + 12, make_float4(v[0].w, v[1].w, v[2].w,  v[3].w));
        __stcs(rec + 13, make_float4(v[4].w, v[5].w, v[6].w,  v[7].w));
        __stcs(rec + 14, make_float4(v[8].w, v[9].w, v[10].w, v[11].w));
        __stcs(rec + 15, make_float4(v[12].w, v[13].w, 0.0f, 0.0f));
    }

    // block stats reduction -> double atomics
    double ds = (double)s, dss = (double)ss;
    #pragma unroll
    for (int o = 16; o > 0; o >>= 1) {
        ds  += __shfl_down_sync(0xFFFFFFFFu, ds,  o);
        dss += __shfl_down_sync(0xFFFFFFFFu, dss, o);
    }
    __shared__ double sh_s[8], sh_ss[8];
    int lane = t & 31, w = t >> 5;
    if (lane == 0) { sh_s[w] = ds; sh_ss[w] = dss; }
    __syncthreads();
    if (t == 0) {
        double ts = 0.0, tss = 0.0;
        for (int k = 0; k < TPB / 32; k++) { ts += sh_s[k]; tss += sh_ss[k]; }
        atomicAdd(&g_sum, ts);
        atomicAdd(&g_sumsq, tss);
    }
}

__global__ void k_stats(const float* __restrict__ far_p,
                        const int* __restrict__ vs_p, int n) {
    double M    = 3.0 * (double)n;
    double mean = g_sum / M;
    double var  = (g_sumsq - g_sum * g_sum / M) / (M - 1.0);   // ddof = 1
    float stdv  = (float)sqrt(var);
    float f     = far_p[0];
    float vs    = (float)vs_p[0];
    float a     = 2.0f * f / vs;
    g_stats = make_float2((float)mean, a / (6.0f * stdv));
}

// Main pass: 4-lane cooperative fetch of each point's 64B AoS record
// (1 cache line/point), full per-point math, coalesced staged output stores.
__global__ void __launch_bounds__(TPB) k_main(const int* __restrict__ coords,
                                              const float* __restrict__ cam,
                                              const float* __restrict__ far_p,
                                              const int* __restrict__ vs_p,
                                              float* __restrict__ out,
                                              int n) {
    __shared__ __align__(16) float4 shr[TPB * 4];   // 16 KB records
    __shared__ __align__(16) float  sh_c[TPB * 9];  // cov staging
    __shared__ __align__(16) float  sh_m[TPB * 3];
    __shared__ __align__(16) float  sh_h[TPB * 3];

    int t  = threadIdx.x;
    int p0 = blockIdx.x * TPB;

    // cooperative record fetch: quad of lanes per point, 8 records/warp-instr
    int gid = t >> 2, q = t & 3;
    #pragma unroll
    for (int it = 0; it < 4; it++) {
        int pl = it * 64 + gid;
        int p  = p0 + pl;
        if (p < n) {
            unsigned idx = g_idx[p];
            shr[pl * 4 + q] = __ldg(g_aos + (size_t)idx * 4 + q);
        }
    }
    __syncthreads();

    int i = p0 + t;
    float op = 0.0f;
    if (i < n) {
        float f  = __ldg(far_p);
        float vs = (float)__ldg(vs_p);
        float a  = 2.0f * f / vs;
        float off = -f + f / vs;
        float2 st = g_stats;
        float cm0 = __ldg(cam + 0), cm1 = __ldg(cam + 1), cm2 = __ldg(cam + 2);

        float4 ra = shr[t * 4 + 0];   // dm0 dm1 dm2 q0
        float4 rb = shr[t * 4 + 1];   // q1 q2 q3 s0
        float4 rc = shr[t * 4 + 2];   // s1 s2 h0 h1
        float4 rd = shr[t * 4 + 3];   // h2 od - -

        int c0 = coords[3 * i + 0];
        int c1 = coords[3 * i + 1];
        int c2 = coords[3 * i + 2];

        sh_m[t * 3 + 0] = (ra.x - st.x) * st.y + (float)c0 * a + cm0 + off;
        sh_m[t * 3 + 1] = (ra.y - st.x) * st.y + (float)c1 * a + cm1 + off;
        sh_m[t * 3 + 2] = (ra.z - st.x) * st.y + (float)c2 * a + cm2 + off;

        float q0 = ra.w, q1 = rb.x, q2 = rb.y, q3 = rb.z;
        float rn = rsqrtf(q0 * q0 + q1 * q1 + q2 * q2 + q3 * q3);
        float r = q0 * rn, x = q1 * rn, y = q2 * rn, z = q3 * rn;
        float R00 = 1.0f - 2.0f * (y * y + z * z);
        float R01 = 2.0f * (x * y - r * z);
        float R02 = 2.0f * (x * z + r * y);
        float R10 = 2.0f * (x * y + r * z);
        float R11 = 1.0f - 2.0f * (x * x + z * z);
        float R12 = 2.0f * (y * z - r * x);
        float R20 = 2.0f * (x * z - r * y);
        float R21 = 2.0f * (y * z + r * x);
        float R22 = 1.0f - 2.0f * (x * x + y * y);

        float sc0 = sigmoidf_(rb.w) * a;
        float sc1 = sigmoidf_(rc.x) * a;
        float sc2 = sigmoidf_(rc.y) * a;
        float v0 = sc0 * sc0, v1 = sc1 * sc1, v2 = sc2 * sc2;

        float* pc = sh_c + t * 9;
        float c01 = R00 * R10 * v0 + R01 * R11 * v1 + R02 * R12 * v2;
        float c02 = R00 * R20 * v0 + R01 * R21 * v1 + R02 * R22 * v2;
        float c12 = R10 * R20 * v0 + R11 * R21 * v1 + R12 * R22 * v2;
        pc[0] = R00 * R00 * v0 + R01 * R01 * v1 + R02 * R02 * v2;
        pc[1] = c01; pc[2] = c02;
        pc[3] = c01;
        pc[4] = R10 * R10 * v0 + R11 * R11 * v1 + R12 * R12 * v2;
        pc[5] = c12;
        pc[6] = c02; pc[7] = c12;
        pc[8] = R20 * R20 * v0 + R21 * R21 * v1 + R22 * R22 * v2;

        sh_h[t * 3 + 0] = rc.z;
        sh_h[t * 3 + 1] = rc.w;
        sh_h[t * 3 + 2] = rd.x;

        op = 1.0f / (1.0f + expf(4.0f - rd.y));
    }
    __syncthreads();

    float* means = out;
    float* cov   = out + 3  * (size_t)n;
    float* harm  = out + 12 * (size_t)n;
    float* opac  = out + 15 * (size_t)n;

    int blk = min(TPB, n - p0);
    if (blk == TPB) {
        const float4* sm4 = (const float4*)sh_m;
        const float4* sh4 = (const float4*)sh_h;
        const float4* sc4 = (const float4*)sh_c;
        float4* dm4 = (float4*)(means + (size_t)p0 * 3);
        float4* dh4 = (float4*)(harm  + (size_t)p0 * 3);
        float4* dc4 = (float4*)(cov   + (size_t)p0 * 9);
        for (int k = t; k < TPB * 3 / 4; k += TPB) {
            __stcs(dm4 + k, sm4[k]);
            __stcs(dh4 + k, sh4[k]);
        }
        for (int k = t; k < TPB * 9 / 4; k += TPB)
            __stcs(dc4 + k, sc4[k]);
    } else {
        for (int k = t; k < blk * 3; k += TPB) {
            __stcs(means + (size_t)p0 * 3 + k, sh_m[k]);
            __stcs(harm  + (size_t)p0 * 3 + k, sh_h[k]);
        }
        for (int k = t; k < blk * 9; k += TPB)
            __stcs(cov + (size_t)p0 * 9 + k, sh_c[k]);
    }
    if (i < n) __stcs(opac + i, op);
}

extern "C" void kernel_launch(void* const* d_in, const int* in_sizes, int n_in,
                              void* d_out, int out_size) {
    const int*   coords = (const int*)d_in[0];
    const float* table  = (const float*)d_in[1];
    const float* cam    = (const float*)d_in[2];
    const float* far_p  = (const float*)d_in[3];
    const int*   vs_p   = (const int*)d_in[4];
    float*       out    = (float*)d_out;

    int n = in_sizes[0] / 3;
    unsigned tsize = (unsigned)(in_sizes[1] / 14);   // 4194304 for this problem

    int pblocks = (n + TPB - 1) / TPB;
    int zblocks = (int)((tsize / 4 + TPB - 1) / TPB);
    int tblocks = (int)((tsize / 4 + TPB - 1) / TPB);

    k_zero      <<<zblocks, TPB>>>(tsize);
    k_hash_count<<<pblocks, TPB>>>(coords, n, tsize);
    k_transpose <<<tblocks, TPB>>>(table, tsize);
    k_stats     <<<1, 1>>>(far_p, vs_p, n);
    k_main      <<<pblocks, TPB>>>(coords, cam, far_p, vs_p, out, n);
}